// round 1
// baseline (speedup 1.0000x reference)
#include <cuda_runtime.h>
#include <cuda_bf16.h>

#define NN   1024
#define BN   4096      // B*N
#define NH   8
#define TI   8
#define TJ   32

// ---- scratch (no allocations allowed) ----
__device__ float g_V[BN*128];
__device__ float g_SKIP[BN*128];
__device__ float g_A1[BN*NH];
__device__ float g_A2[BN*NH];
__device__ float g_ATTG[4*NH];

// ---- packed f32x2 helpers (Blackwell) ----
__device__ __forceinline__ unsigned long long ffma2(unsigned long long a,
                                                    unsigned long long b,
                                                    unsigned long long c) {
    unsigned long long d;
    asm("fma.rn.f32x2 %0, %1, %2, %3;" : "=l"(d) : "l"(a), "l"(b), "l"(c));
    return d;
}
__device__ __forceinline__ unsigned long long pack2(float x, float y) {
    unsigned long long r;
    asm("mov.b64 %0, {%1, %2};" : "=l"(r) : "f"(x), "f"(y));
    return r;
}
__device__ __forceinline__ float2 unpack2(unsigned long long v) {
    float2 r;
    asm("mov.b64 {%0, %1}, %2;" : "=f"(r.x), "=f"(r.y) : "l"(v));
    return r;
}

// =====================================================================
// Kernel A: per-node GEMMs.  values = z@m_w+m_b, skip = z@skip_w+skip_b,
// att1 = z@a1_w+a1_b, att2 = z@a2_w+a2_b.  16 rows per block.
// =====================================================================
__global__ __launch_bounds__(256) void gat_prep(
    const float* __restrict__ node, const float* __restrict__ hidden,
    const float* __restrict__ m_w,  const float* __restrict__ m_b,
    const float* __restrict__ skip_w, const float* __restrict__ skip_b,
    const float* __restrict__ a1_w, const float* __restrict__ a1_b,
    const float* __restrict__ a2_w, const float* __restrict__ a2_b)
{
    __shared__ float zs[16][256];
    __shared__ float ws_v[32*128];
    __shared__ float ws_s[32*128];

    const int tid = threadIdx.x;
    const int r0  = blockIdx.x * 16;

    // stage z = [node | hidden] rows
    for (int t = tid; t < 16*64; t += 256) {
        int r = t >> 6, q = t & 63;
        int rowg = r0 + r;
        float4 v;
        if (q < 32) v = ((const float4*)node)[rowg*32 + q];
        else        v = ((const float4*)hidden)[rowg*32 + (q - 32)];
        *(float4*)&zs[r][q*4] = v;
    }

    const int row = tid >> 4;
    const int c0  = (tid & 15) * 8;

    unsigned long long av[4], as2[4];
    {
        ulonglong2 t0 = *(const ulonglong2*)&m_b[c0];
        ulonglong2 t1 = *(const ulonglong2*)&m_b[c0+4];
        av[0]=t0.x; av[1]=t0.y; av[2]=t1.x; av[3]=t1.y;
        ulonglong2 s0 = *(const ulonglong2*)&skip_b[c0];
        ulonglong2 s1 = *(const ulonglong2*)&skip_b[c0+4];
        as2[0]=s0.x; as2[1]=s0.y; as2[2]=s1.x; as2[3]=s1.y;
    }

    for (int kk = 0; kk < 256; kk += 32) {
        __syncthreads();
        for (int t = tid; t < 1024; t += 256) {
            ((float4*)ws_v)[t] = ((const float4*)m_w)[kk*32 + t];
            ((float4*)ws_s)[t] = ((const float4*)skip_w)[kk*32 + t];
        }
        __syncthreads();
        #pragma unroll
        for (int k = 0; k < 32; ++k) {
            float zv = zs[row][kk + k];
            unsigned long long zz = pack2(zv, zv);
            ulonglong2 w0 = *(const ulonglong2*)&ws_v[k*128 + c0];
            ulonglong2 w1 = *(const ulonglong2*)&ws_v[k*128 + c0 + 4];
            ulonglong2 s0 = *(const ulonglong2*)&ws_s[k*128 + c0];
            ulonglong2 s1 = *(const ulonglong2*)&ws_s[k*128 + c0 + 4];
            av[0]  = ffma2(zz, w0.x, av[0]);
            av[1]  = ffma2(zz, w0.y, av[1]);
            av[2]  = ffma2(zz, w1.x, av[2]);
            av[3]  = ffma2(zz, w1.y, av[3]);
            as2[0] = ffma2(zz, s0.x, as2[0]);
            as2[1] = ffma2(zz, s0.y, as2[1]);
            as2[2] = ffma2(zz, s1.x, as2[2]);
            as2[3] = ffma2(zz, s1.y, as2[3]);
        }
    }
    {
        int rowg = r0 + row;
        ulonglong2 o0; o0.x = av[0]; o0.y = av[1];
        ulonglong2 o1; o1.x = av[2]; o1.y = av[3];
        *(ulonglong2*)&g_V[rowg*128 + c0]     = o0;
        *(ulonglong2*)&g_V[rowg*128 + c0 + 4] = o1;
        ulonglong2 p0; p0.x = as2[0]; p0.y = as2[1];
        ulonglong2 p1; p1.x = as2[2]; p1.y = as2[3];
        *(ulonglong2*)&g_SKIP[rowg*128 + c0]     = p0;
        *(ulonglong2*)&g_SKIP[rowg*128 + c0 + 4] = p1;
    }

    // ---- att1 / att2 (reuse weight smem) ----
    __syncthreads();
    for (int t = tid; t < 2048; t += 256) {
        ws_v[t] = a1_w[t];
        ws_s[t] = a2_w[t];
    }
    __syncthreads();
    const int slot = tid & 15;
    const int r2   = tid >> 4;
    const int h    = slot & 7;
    const float* w = (slot < 8) ? ws_v : ws_s;
    float acc = (slot < 8) ? a1_b[h] : a2_b[h];
    #pragma unroll 8
    for (int k = 0; k < 256; ++k)
        acc = fmaf(zs[r2][k], w[k*8 + h], acc);
    int rg2 = r0 + r2;
    if (slot < 8) g_A1[rg2*8 + h] = acc;
    else          g_A2[rg2*8 + h] = acc;
}

// =====================================================================
// Kernel B: att_g[b,h] = graph_fts[b]@ag_w + ag_b
// =====================================================================
__global__ void gat_attg(const float* __restrict__ graph,
                         const float* __restrict__ ag_w,
                         const float* __restrict__ ag_b)
{
    int t = threadIdx.x;
    if (t < 32) {
        int b = t >> 3, h = t & 7;
        float acc = ag_b[h];
        #pragma unroll 8
        for (int k = 0; k < 128; ++k)
            acc = fmaf(graph[b*128 + k], ag_w[k*8 + h], acc);
        g_ATTG[t] = acc;
    }
}

// =====================================================================
// Kernel C: fused logits + leaky_relu + mask + softmax(fixed shift) +
//           weighted value sum + skip + relu.
// Block = (b, 8 rows i).  Thread owns (i_local, h, j-parity half).
// =====================================================================
__global__ __launch_bounds__(128) void gat_attn(
    const float* __restrict__ edge, const int* __restrict__ adj,
    const float* __restrict__ ae_w, const float* __restrict__ ae_b,
    float* __restrict__ out)
{
    __shared__ float edge_s[TI][TJ*16 + 4];   // pad -> distinct bank phases per i
    __shared__ float vals_s[NH][TJ*16 + 4];   // per-head rows  -> conflict-free
    __shared__ float att2_s[TJ*NH];
    __shared__ int   adj_s[TI][TJ + 1];
    __shared__ float red_s[64][18];

    const int tid  = threadIdx.x;
    const int b    = blockIdx.x >> 7;         // 128 blocks per batch
    const int it   = blockIdx.x & 127;
    const int i0   = it * TI;
    const int pair = tid & 63, half = tid >> 6;
    const int il   = pair >> 3, h = pair & 7;
    const int ig   = i0 + il;

    unsigned long long aw2[8];
    #pragma unroll
    for (int q = 0; q < 8; ++q)
        aw2[q] = pack2(ae_w[(2*q)*8 + h], ae_w[(2*q+1)*8 + h]);
    const float base = g_A1[(b*NN + ig)*8 + h] + g_ATTG[b*8 + h] + ae_b[h];

    unsigned long long acc[8];
    #pragma unroll
    for (int q = 0; q < 8; ++q) acc[q] = 0ull;
    float s = 0.0f;

    for (int j0 = 0; j0 < NN; j0 += TJ) {
        __syncthreads();
        // edge tile: TI x TJ x 16 floats (read exactly once from HBM)
        for (int t = tid; t < TI*TJ*4; t += 128) {
            int i = t >> 7, q = t & 127;
            float4 v = ((const float4*)edge)[((b*NN + i0 + i)*NN + j0)*4 + q];
            *(float4*)&edge_s[i][q*4] = v;
        }
        // value tile, swizzled to per-head rows (L2-resident source)
        for (int t = tid; t < TJ*32; t += 128) {
            int j = t >> 5, c4 = t & 31;
            float4 v = *(const float4*)&g_V[(b*NN + j0 + j)*128 + c4*4];
            int hh = c4 >> 2, d4 = c4 & 3;
            *(float4*)&vals_s[hh][j*16 + d4*4] = v;
        }
        for (int t = tid; t < TJ*8; t += 128)
            att2_s[t] = g_A2[(b*NN + j0)*8 + t];
        for (int t = tid; t < TI*TJ; t += 128) {
            int i = t >> 5, j = t & 31;
            adj_s[i][j] = adj[(b*NN + i0 + i)*NN + j0 + j];
        }
        __syncthreads();

        #pragma unroll 2
        for (int jj = half; jj < TJ; jj += 2) {
            ulonglong2 e0 = *(const ulonglong2*)&edge_s[il][jj*16];
            ulonglong2 e1 = *(const ulonglong2*)&edge_s[il][jj*16 + 4];
            ulonglong2 e2 = *(const ulonglong2*)&edge_s[il][jj*16 + 8];
            ulonglong2 e3 = *(const ulonglong2*)&edge_s[il][jj*16 + 12];
            unsigned long long sA = ffma2(e0.x, aw2[0], 0ull);
            unsigned long long sB = ffma2(e0.y, aw2[1], 0ull);
            sA = ffma2(e1.x, aw2[2], sA);
            sB = ffma2(e1.y, aw2[3], sB);
            sA = ffma2(e2.x, aw2[4], sA);
            sB = ffma2(e2.y, aw2[5], sB);
            sA = ffma2(e3.x, aw2[6], sA);
            sB = ffma2(e3.y, aw2[7], sB);
            float2 fa = unpack2(sA), fb = unpack2(sB);
            float att_e = (fa.x + fa.y) + (fb.x + fb.y);

            float logit = base + att2_s[jj*8 + h] + att_e;
            float l = fmaxf(logit, 0.01f * logit);        // leaky_relu
            float t = l * 1.4426950408889634f;            // -> log2 domain
            t = adj_s[il][jj] ? t : -60.0f;               // mask (exp2 -> ~1e-18)
            t = fminf(t, 80.0f);

            // fast exp2 on the FMA pipe (avoid MUFU bottleneck)
            float r = __fadd_rn(t, 12582912.0f);          // 1.5*2^23 magic
            float f = __fsub_rn(t, __fsub_rn(r, 12582912.0f));
            int ebits = __float_as_int(r);
            float scale = __int_as_float((ebits - 0x4B3FFF81) << 23);
            float pe = 1.3333558e-3f;
            pe = fmaf(pe, f, 9.6181291e-3f);
            pe = fmaf(pe, f, 5.5504109e-2f);
            pe = fmaf(pe, f, 2.4022651e-1f);
            pe = fmaf(pe, f, 6.9314718e-1f);
            pe = fmaf(pe, f, 1.0f);
            float p = pe * scale;

            s += p;
            unsigned long long pp = pack2(p, p);
            ulonglong2 v0 = *(const ulonglong2*)&vals_s[h][jj*16];
            ulonglong2 v1 = *(const ulonglong2*)&vals_s[h][jj*16 + 4];
            ulonglong2 v2 = *(const ulonglong2*)&vals_s[h][jj*16 + 8];
            ulonglong2 v3 = *(const ulonglong2*)&vals_s[h][jj*16 + 12];
            acc[0] = ffma2(pp, v0.x, acc[0]);
            acc[1] = ffma2(pp, v0.y, acc[1]);
            acc[2] = ffma2(pp, v1.x, acc[2]);
            acc[3] = ffma2(pp, v1.y, acc[3]);
            acc[4] = ffma2(pp, v2.x, acc[4]);
            acc[5] = ffma2(pp, v2.y, acc[5]);
            acc[6] = ffma2(pp, v3.x, acc[6]);
            acc[7] = ffma2(pp, v3.y, acc[7]);
        }
    }

    // combine the two j-parity halves (fixed-shift softmax => plain adds)
    float accf[16];
    #pragma unroll
    for (int q = 0; q < 8; ++q) {
        float2 fv = unpack2(acc[q]);
        accf[2*q] = fv.x; accf[2*q+1] = fv.y;
    }
    __syncthreads();
    if (half) {
        #pragma unroll
        for (int d = 0; d < 16; ++d) red_s[pair][d] = accf[d];
        red_s[pair][16] = s;
    }
    __syncthreads();
    if (!half) {
        #pragma unroll
        for (int d = 0; d < 16; ++d) accf[d] += red_s[pair][d];
        s += red_s[pair][16];
        float inv = 1.0f / s;
        int ob = (b*NN + ig)*128 + h*16;
        #pragma unroll
        for (int q = 0; q < 4; ++q) {
            float4 sk = *(const float4*)&g_SKIP[ob + q*4];
            float4 o;
            o.x = fmaxf(fmaf(accf[q*4+0], inv, sk.x), 0.0f);
            o.y = fmaxf(fmaf(accf[q*4+1], inv, sk.y), 0.0f);
            o.z = fmaxf(fmaf(accf[q*4+2], inv, sk.z), 0.0f);
            o.w = fmaxf(fmaf(accf[q*4+3], inv, sk.w), 0.0f);
            *(float4*)&out[ob + q*4] = o;
        }
    }
}

// =====================================================================
extern "C" void kernel_launch(void* const* d_in, const int* in_sizes, int n_in,
                              void* d_out, int out_size)
{
    const float* node   = (const float*)d_in[0];
    const float* edge   = (const float*)d_in[1];
    const float* graph  = (const float*)d_in[2];
    const int*   adj    = (const int*)  d_in[3];
    const float* hidden = (const float*)d_in[4];
    const float* m_w    = (const float*)d_in[5];
    const float* m_b    = (const float*)d_in[6];
    const float* skip_w = (const float*)d_in[7];
    const float* skip_b = (const float*)d_in[8];
    const float* a1_w   = (const float*)d_in[9];
    const float* a1_b   = (const float*)d_in[10];
    const float* a2_w   = (const float*)d_in[11];
    const float* a2_b   = (const float*)d_in[12];
    const float* ae_w   = (const float*)d_in[13];
    const float* ae_b   = (const float*)d_in[14];
    const float* ag_w   = (const float*)d_in[15];
    const float* ag_b   = (const float*)d_in[16];
    float* out = (float*)d_out;

    gat_prep<<<BN/16, 256>>>(node, hidden, m_w, m_b, skip_w, skip_b,
                             a1_w, a1_b, a2_w, a2_b);
    gat_attg<<<1, 32>>>(graph, ag_w, ag_b);
    gat_attn<<<4 * (NN/TI), 128>>>(edge, adj, ae_w, ae_b, out);
}